// round 5
// baseline (speedup 1.0000x reference)
#include <cuda_runtime.h>
#include <stdint.h>
#include <math.h>

#define NE 768
#define LM 1024
#define LS 1024
#define BB 4
#define NH 12
#define HD 64
#define NT (BB*LM)

// ---------------- scratch ------------------------------------------------------
__device__ float g_sn[NT*NE];
__device__ float g_xn[NT*NE];
__device__ float g_q [NT*NE];
__device__ float g_k [NT*NE];
__device__ float g_v [NT*NE];
__device__ float g_y [NT*NE];
__device__ float g_x2[NT*NE];
__device__ float g_h1[NT*NE];
__device__ float g_h2[NT*4*NE];
__device__ int   g_code[NT];

__device__ __forceinline__ uint32_t f2tf32(float x) {
    uint32_t r;
    asm("cvt.rna.tf32.f32 %0, %1;" : "=r"(r) : "f"(x));
    return r;
}
__device__ __forceinline__ float roundtf(float x) { return __uint_as_float(f2tf32(x)); }

// ---------------- fuse_embed scan ----------------------------------------------
__global__ void scan_kernel(const int* __restrict__ mod_idx, int* __restrict__ code) {
    int b = blockIdx.x;
    __shared__ int s[LS];
    int t = threadIdx.x;
    int idx = mod_idx[b*LS + t];
    int is2 = (idx == 2) ? 1 : 0;
    s[t] = is2;
    __syncthreads();
    for (int off = 1; off < LS; off <<= 1) {
        int v = (t >= off) ? s[t - off] : 0;
        __syncthreads();
        s[t] += v;
        __syncthreads();
    }
    int c2 = s[t];
    int occ = is2 ? (c2 - 1) : (t + 1 - c2 - 1);
    if (occ < 0) occ = 0;
    if (occ > LS/2 - 1) occ = LS/2 - 1;
    code[b*LS + t] = ((b*(LS/2) + occ) << 1) | (is2 ? 0 : 1);
}

// ---------------- LayerNorm (outputs tf32-rounded) ------------------------------
__device__ __forceinline__ void ln_body(const float* __restrict__ p,
                                        const float* __restrict__ w,
                                        const float* __restrict__ bias,
                                        float* __restrict__ o) {
    int t = threadIdx.x;
    float v0 = p[t], v1 = p[t+256], v2 = p[t+512];
    float s = v0 + v1 + v2;
    float q = v0*v0 + v1*v1 + v2*v2;
    __shared__ float sb1[8], sb2[8];
    int lane = t & 31, wrp = t >> 5;
    #pragma unroll
    for (int o2 = 16; o2; o2 >>= 1) {
        s += __shfl_xor_sync(0xffffffffu, s, o2);
        q += __shfl_xor_sync(0xffffffffu, q, o2);
    }
    if (lane == 0) { sb1[wrp] = s; sb2[wrp] = q; }
    __syncthreads();
    if (t == 0) {
        float S = 0.f, Q = 0.f;
        #pragma unroll
        for (int i = 0; i < 8; i++) { S += sb1[i]; Q += sb2[i]; }
        sb1[0] = S; sb2[0] = Q;
    }
    __syncthreads();
    float mean = sb1[0] * (1.0f/NE);
    float var  = sb2[0] * (1.0f/NE) - mean*mean;
    float r = rsqrtf(var + 1e-5f);
    o[t]     = roundtf((v0 - mean) * r * w[t]     + bias[t]);
    o[t+256] = roundtf((v1 - mean) * r * w[t+256] + bias[t+256]);
    o[t+512] = roundtf((v2 - mean) * r * w[t+512] + bias[t+512]);
}

__global__ void ln_kernel(const float* __restrict__ in, const float* __restrict__ w,
                          const float* __restrict__ bias, float* __restrict__ out) {
    int row = blockIdx.x;
    ln_body(in + (size_t)row*NE, w, bias, out + (size_t)row*NE);
}

__global__ void gather_ln_kernel(const int* __restrict__ code,
                                 const float* __restrict__ m2, const float* __restrict__ m3,
                                 const float* __restrict__ w,  const float* __restrict__ bias,
                                 float* __restrict__ out) {
    int row = blockIdx.x;
    int c = code[row];
    const float* src = ((c & 1) ? m3 : m2) + (size_t)(c >> 1) * NE;
    ln_body(src, w, bias, out + (size_t)row*NE);
}

// ---------------- tf32 tensor-core GEMM body -----------------------------------
// Weights are fed as raw fp32 bits: HMMA.tf32 ignores low 13 mantissa bits
// (RZ truncation to tf32). A operands are pre-rounded by producer kernels.
// act bit0 = gelu, bit1 = round output to tf32
#define BM 128
#define BN 128
#define BK 32
#define KS2 (BK+4)                       // 36 floats row stride
#define GEMM_SMEM (2*2*BM*KS2*4)         // 2 matrices * 2 stages = 73728 B

__device__ __forceinline__ void cp16(void* smem, const void* g) {
    uint32_t s = (uint32_t)__cvta_generic_to_shared(smem);
    asm volatile("cp.async.ca.shared.global [%0], [%1], 16;" :: "r"(s), "l"(g));
}

__device__ __forceinline__ void gemm_body(
    const float* A, const float* W, const float* bias, const float* res,
    float* C, int N, int K, int act)
{
    extern __shared__ float sm[];
    float* As = sm;                       // [2][BM][KS2]
    float* Ws = sm + 2*BM*KS2;            // [2][BN][KS2]

    int tid = threadIdx.x, lane = tid & 31, warp = tid >> 5;
    int g = lane >> 2, c = lane & 3;
    int wm = (warp >> 2) * 64;
    int wn = (warp & 3) * 32;
    int bm = blockIdx.y * BM, bn = blockIdx.x * BN;

    float acc[4][4][4];
    #pragma unroll
    for (int mi = 0; mi < 4; mi++)
        #pragma unroll
        for (int ni = 0; ni < 4; ni++)
            #pragma unroll
            for (int r = 0; r < 4; r++) acc[mi][ni][r] = 0.f;

    const int nt = K / BK;

    // stage load: 1024 float4 per matrix, 4 per thread
    #pragma unroll
    for (int i = 0; i < 4; i++) {
        int f = tid + i*256;
        int m = f >> 3, kk = (f & 7) << 2;
        cp16(&As[0*BM*KS2 + m*KS2 + kk], A + (size_t)(bm+m)*K + kk);
        cp16(&Ws[0*BN*KS2 + m*KS2 + kk], W + (size_t)(bn+m)*K + kk);
    }
    asm volatile("cp.async.commit_group;");

    for (int kt = 0; kt < nt; kt++) {
        int buf = kt & 1;
        if (kt + 1 < nt) {
            int k0 = (kt+1) * BK;
            int nb = buf ^ 1;
            #pragma unroll
            for (int i = 0; i < 4; i++) {
                int f = tid + i*256;
                int m = f >> 3, kk = (f & 7) << 2;
                cp16(&As[nb*BM*KS2 + m*KS2 + kk], A + (size_t)(bm+m)*K + k0 + kk);
                cp16(&Ws[nb*BN*KS2 + m*KS2 + kk], W + (size_t)(bn+m)*K + k0 + kk);
            }
            asm volatile("cp.async.commit_group;");
            asm volatile("cp.async.wait_group 1;");
        } else {
            asm volatile("cp.async.wait_group 0;");
        }
        __syncthreads();

        const float* Ab = As + buf*BM*KS2;
        const float* Wb = Ws + buf*BN*KS2;
        #pragma unroll
        for (int ks = 0; ks < BK; ks += 8) {
            uint32_t af[4][4], bf[4][2];
            #pragma unroll
            for (int mi = 0; mi < 4; mi++) {
                int r = wm + mi*16;
                af[mi][0] = __float_as_uint(Ab[(r+g  )*KS2 + ks + c  ]);
                af[mi][1] = __float_as_uint(Ab[(r+g+8)*KS2 + ks + c  ]);
                af[mi][2] = __float_as_uint(Ab[(r+g  )*KS2 + ks + c+4]);
                af[mi][3] = __float_as_uint(Ab[(r+g+8)*KS2 + ks + c+4]);
            }
            #pragma unroll
            for (int ni = 0; ni < 4; ni++) {
                int cn = wn + ni*8;
                bf[ni][0] = __float_as_uint(Wb[(cn+g)*KS2 + ks + c  ]);
                bf[ni][1] = __float_as_uint(Wb[(cn+g)*KS2 + ks + c+4]);
            }
            #pragma unroll
            for (int mi = 0; mi < 4; mi++)
                #pragma unroll
                for (int ni = 0; ni < 4; ni++) {
                    asm volatile(
                        "mma.sync.aligned.m16n8k8.row.col.f32.tf32.tf32.f32 "
                        "{%0,%1,%2,%3}, {%4,%5,%6,%7}, {%8,%9}, {%0,%1,%2,%3};"
                        : "+f"(acc[mi][ni][0]), "+f"(acc[mi][ni][1]),
                          "+f"(acc[mi][ni][2]), "+f"(acc[mi][ni][3])
                        : "r"(af[mi][0]), "r"(af[mi][1]), "r"(af[mi][2]), "r"(af[mi][3]),
                          "r"(bf[ni][0]), "r"(bf[ni][1]));
                }
        }
        __syncthreads();
    }

    #pragma unroll
    for (int mi = 0; mi < 4; mi++) {
        #pragma unroll
        for (int half = 0; half < 2; half++) {
            int gm = bm + wm + mi*16 + g + half*8;
            #pragma unroll
            for (int ni = 0; ni < 4; ni++) {
                int gn = bn + wn + ni*8 + c*2;
                float v0 = acc[mi][ni][half*2+0] + bias[gn];
                float v1 = acc[mi][ni][half*2+1] + bias[gn+1];
                if (res) {
                    const float2 r2 = *(const float2*)(res + (size_t)gm*N + gn);
                    v0 += r2.x; v1 += r2.y;
                }
                if (act & 1) {
                    v0 = 0.5f * v0 * (1.0f + erff(v0 * 0.70710678118654752f));
                    v1 = 0.5f * v1 * (1.0f + erff(v1 * 0.70710678118654752f));
                }
                if (act & 2) { v0 = roundtf(v0); v1 = roundtf(v1); }
                *(float2*)(C + (size_t)gm*N + gn) = make_float2(v0, v1);
            }
        }
    }
}

__global__ __launch_bounds__(256) void mma_gemm(
    const float* A, const float* W, const float* bias, const float* res,
    float* C, int N, int K, int act)
{
    gemm_body(A, W, bias, res, C, N, K, act);
}

__global__ __launch_bounds__(256) void mma_gemm_qkv(
    const float* xn, const float* sn,
    const float* wq, const float* wk, const float* wv,
    const float* qb, const float* kb, const float* vb,
    float* q, float* k, float* v)
{
    int z = blockIdx.z;
    const float* A = (z == 0) ? xn : sn;
    const float* W = (z == 0) ? wq : (z == 1) ? wk : wv;
    const float* B = (z == 0) ? qb : (z == 1) ? kb : vb;
    float*       C = (z == 0) ? q  : (z == 1) ? k  : v;
    gemm_body(A, W, B, nullptr, C, NE, NE, 2);
}

// ---------------- tensor-core flash attention ----------------------------------
#define AP 68
#define ATTN_SMEM ((1024 + 64 + 4*64*AP) * 4)

__global__ __launch_bounds__(128) void attn_kernel(
    const float* __restrict__ Q, const float* __restrict__ Kg, const float* __restrict__ Vg,
    const float* __restrict__ age, const float* __restrict__ mod_age,
    float* __restrict__ Y)
{
    extern __shared__ float smn[];
    float* ma = smn;
    int*   km = (int*)(smn + 1024);
    float* Qs = smn + 1024 + 64;
    float* Ks = Qs + 64*AP;
    float* Vs = Ks + 64*AP;
    float* Ps = Vs + 64*AP;

    int blk = blockIdx.x;
    int qt   = blk & 15;
    int hd_i = (blk >> 4) % NH;
    int b    = blk / (16*NH);
    int tid  = threadIdx.x;
    int lane = tid & 31, warp = tid >> 5;
    int g = lane >> 2, c = lane & 3;
    int wr = warp * 16;

    for (int i = tid; i < LS; i += 128) ma[i] = mod_age[b*LS + i];
    __syncthreads();

    if (tid < 64) {
        float a = age[b*LM + qt*64 + tid];
        int lo = 0, hi = LS;
        while (lo < hi) { int mid = (lo+hi) >> 1; if (ma[mid] <= a) lo = mid+1; else hi = mid; }
        km[tid] = lo;
    }
    __syncthreads();
    int kmax_blk = 0;
    #pragma unroll 8
    for (int i = 0; i < 64; i++) kmax_blk = max(kmax_blk, km[i]);

    int tq = b*LM + qt*64;
    {
        int r = tid >> 1, half = (tid & 1) * 32;
        const float4* src = (const float4*)(Q + (size_t)(tq+r)*NE + hd_i*HD + half);
        float4* dst = (float4*)(Qs + r*AP + half);
        #pragma unroll
        for (int i = 0; i < 8; i++) dst[i] = src[i];
    }

    float m0 = -1e30f, m1 = -1e30f, l0 = 0.f, l1 = 0.f;
    float Oacc[8][4];
    #pragma unroll
    for (int ni = 0; ni < 8; ni++)
        #pragma unroll
        for (int r = 0; r < 4; r++) Oacc[ni][r] = 0.f;

    int km0 = km[wr + g];
    int km1 = km[wr + g + 8];

    for (int j0 = 0; j0 < kmax_blk; j0 += 64) {
        int rows = min(64, kmax_blk - j0);
        __syncthreads();
        {
            int r = tid >> 1, half = (tid & 1) * 32;
            float4* dk = (float4*)(Ks + r*AP + half);
            float4* dv = (float4*)(Vs + r*AP + half);
            if (r < rows) {
                const float4* sk = (const float4*)(Kg + (size_t)(b*LS + j0 + r)*NE + hd_i*HD + half);
                const float4* sv = (const float4*)(Vg + (size_t)(b*LS + j0 + r)*NE + hd_i*HD + half);
                #pragma unroll
                for (int i = 0; i < 8; i++) { dk[i] = sk[i]; dv[i] = sv[i]; }
            } else {
                float4 z = make_float4(0.f,0.f,0.f,0.f);
                #pragma unroll
                for (int i = 0; i < 8; i++) { dk[i] = z; dv[i] = z; }
            }
        }
        __syncthreads();

        float Sacc[8][4];
        #pragma unroll
        for (int ni = 0; ni < 8; ni++)
            #pragma unroll
            for (int r = 0; r < 4; r++) Sacc[ni][r] = 0.f;

        #pragma unroll
        for (int kk = 0; kk < 64; kk += 8) {
            uint32_t a0 = __float_as_uint(Qs[(wr+g  )*AP + kk + c  ]);
            uint32_t a1 = __float_as_uint(Qs[(wr+g+8)*AP + kk + c  ]);
            uint32_t a2 = __float_as_uint(Qs[(wr+g  )*AP + kk + c+4]);
            uint32_t a3 = __float_as_uint(Qs[(wr+g+8)*AP + kk + c+4]);
            #pragma unroll
            for (int ni = 0; ni < 8; ni++) {
                uint32_t b0 = __float_as_uint(Ks[(ni*8+g)*AP + kk + c  ]);
                uint32_t b1 = __float_as_uint(Ks[(ni*8+g)*AP + kk + c+4]);
                asm volatile(
                    "mma.sync.aligned.m16n8k8.row.col.f32.tf32.tf32.f32 "
                    "{%0,%1,%2,%3}, {%4,%5,%6,%7}, {%8,%9}, {%0,%1,%2,%3};"
                    : "+f"(Sacc[ni][0]), "+f"(Sacc[ni][1]), "+f"(Sacc[ni][2]), "+f"(Sacc[ni][3])
                    : "r"(a0), "r"(a1), "r"(a2), "r"(a3), "r"(b0), "r"(b1));
            }
        }

        #pragma unroll
        for (int hh = 0; hh < 2; hh++) {
            int row = wr + g + hh*8;
            int kmr = hh ? km1 : km0;
            float mold = hh ? m1 : m0;

            float mx = -1e30f;
            #pragma unroll
            for (int ni = 0; ni < 8; ni++) {
                int c0 = j0 + ni*8 + 2*c;
                float s0 = (c0   < kmr) ? Sacc[ni][hh*2  ] * 0.125f : -1e30f;
                float s1 = (c0+1 < kmr) ? Sacc[ni][hh*2+1] * 0.125f : -1e30f;
                Sacc[ni][hh*2] = s0; Sacc[ni][hh*2+1] = s1;
                mx = fmaxf(mx, fmaxf(s0, s1));
            }
            mx = fmaxf(mx, __shfl_xor_sync(0xffffffffu, mx, 1));
            mx = fmaxf(mx, __shfl_xor_sync(0xffffffffu, mx, 2));
            float mnew = fmaxf(mold, mx);
            float alpha = __expf(mold - mnew);

            float lsum = 0.f;
            #pragma unroll
            for (int ni = 0; ni < 8; ni++) {
                int c0 = j0 + ni*8 + 2*c;
                float p0 = (c0   < kmr) ? __expf(Sacc[ni][hh*2  ] - mnew) : 0.f;
                float p1 = (c0+1 < kmr) ? __expf(Sacc[ni][hh*2+1] - mnew) : 0.f;
                lsum += p0 + p1;
                *(float2*)(Ps + row*AP + ni*8 + 2*c) = make_float2(roundtf(p0), roundtf(p1));
            }
            lsum += __shfl_xor_sync(0xffffffffu, lsum, 1);
            lsum += __shfl_xor_sync(0xffffffffu, lsum, 2);

            if (hh) { l1 = l1*alpha + lsum; m1 = mnew; }
            else    { l0 = l0*alpha + lsum; m0 = mnew; }
            #pragma unroll
            for (int ni = 0; ni < 8; ni++) {
                Oacc[ni][hh*2  ] *= alpha;
                Oacc[ni][hh*2+1] *= alpha;
            }
        }
        __syncwarp();

        #pragma unroll
        for (int kk = 0; kk < 64; kk += 8) {
            uint32_t a0 = __float_as_uint(Ps[(wr+g  )*AP + kk + c  ]);
            uint32_t a1 = __float_as_uint(Ps[(wr+g+8)*AP + kk + c  ]);
            uint32_t a2 = __float_as_uint(Ps[(wr+g  )*AP + kk + c+4]);
            uint32_t a3 = __float_as_uint(Ps[(wr+g+8)*AP + kk + c+4]);
            #pragma unroll
            for (int ni = 0; ni < 8; ni++) {
                uint32_t b0 = __float_as_uint(Vs[(kk+c  )*AP + ni*8 + g]);
                uint32_t b1 = __float_as_uint(Vs[(kk+c+4)*AP + ni*8 + g]);
                asm volatile(
                    "mma.sync.aligned.m16n8k8.row.col.f32.tf32.tf32.f32 "
                    "{%0,%1,%2,%3}, {%4,%5,%6,%7}, {%8,%9}, {%0,%1,%2,%3};"
                    : "+f"(Oacc[ni][0]), "+f"(Oacc[ni][1]), "+f"(Oacc[ni][2]), "+f"(Oacc[ni][3])
                    : "r"(a0), "r"(a1), "r"(a2), "r"(a3), "r"(b0), "r"(b1));
            }
        }
    }

    float inv0 = (l0 > 0.f) ? 1.0f / l0 : 0.f;
    float inv1 = (l1 > 0.f) ? 1.0f / l1 : 0.f;
    #pragma unroll
    for (int hh = 0; hh < 2; hh++) {
        int row = wr + g + hh*8;
        float inv = hh ? inv1 : inv0;
        float* yp = Y + (size_t)(tq + row)*NE + hd_i*HD;
        #pragma unroll
        for (int ni = 0; ni < 8; ni++) {
            float v0 = roundtf(Oacc[ni][hh*2  ] * inv);
            float v1 = roundtf(Oacc[ni][hh*2+1] * inv);
            *(float2*)(yp + ni*8 + 2*c) = make_float2(v0, v1);
        }
    }
}

// ---------------- launch -------------------------------------------------------
extern "C" void kernel_launch(void* const* d_in, const int* in_sizes, int n_in,
                              void* d_out, int out_size) {
    const float* x       = (const float*)d_in[0];
    const float* age     = (const float*)d_in[1];
    const int*   mod_idx = (const int*)  d_in[2];
    const float* mod_age = (const float*)d_in[3];
    const float* m2      = (const float*)d_in[4];
    const float* m3      = (const float*)d_in[5];
    const float* ln0_w = (const float*)d_in[6],  *ln0_b = (const float*)d_in[7];
    const float* ln1_w = (const float*)d_in[8],  *ln1_b = (const float*)d_in[9];
    const float* ln2_w = (const float*)d_in[10], *ln2_b = (const float*)d_in[11];
    const float* q_w  = (const float*)d_in[12], *q_b  = (const float*)d_in[13];
    const float* k_w  = (const float*)d_in[14], *k_b  = (const float*)d_in[15];
    const float* v_w  = (const float*)d_in[16], *v_b  = (const float*)d_in[17];
    const float* c_w  = (const float*)d_in[18], *c_b  = (const float*)d_in[19];
    const float* fc_w = (const float*)d_in[20], *fc_b = (const float*)d_in[21];
    const float* pj_w = (const float*)d_in[22], *pj_b = (const float*)d_in[23];
    float* out = (float*)d_out;

    float *p_sn,*p_xn,*p_q,*p_k,*p_v,*p_y,*p_x2,*p_h1,*p_h2;
    int *p_code;
    cudaGetSymbolAddress((void**)&p_sn,  g_sn);
    cudaGetSymbolAddress((void**)&p_xn,  g_xn);
    cudaGetSymbolAddress((void**)&p_q,   g_q);
    cudaGetSymbolAddress((void**)&p_k,   g_k);
    cudaGetSymbolAddress((void**)&p_v,   g_v);
    cudaGetSymbolAddress((void**)&p_y,   g_y);
    cudaGetSymbolAddress((void**)&p_x2,  g_x2);
    cudaGetSymbolAddress((void**)&p_h1,  g_h1);
    cudaGetSymbolAddress((void**)&p_h2,  g_h2);
    cudaGetSymbolAddress((void**)&p_code, g_code);

    static bool attr_set = false;
    if (!attr_set) {
        cudaFuncSetAttribute(attn_kernel, cudaFuncAttributeMaxDynamicSharedMemorySize, ATTN_SMEM);
        cudaFuncSetAttribute(mma_gemm, cudaFuncAttributeMaxDynamicSharedMemorySize, GEMM_SMEM);
        cudaFuncSetAttribute(mma_gemm_qkv, cudaFuncAttributeMaxDynamicSharedMemorySize, GEMM_SMEM);
        attr_set = true;
    }

    scan_kernel<<<BB, LS>>>(mod_idx, p_code);
    gather_ln_kernel<<<NT, 256>>>(p_code, m2, m3, ln0_w, ln0_b, p_sn);
    ln_kernel<<<NT, 256>>>(x, ln1_w, ln1_b, p_xn);

    dim3 gqkv(NE/128, NT/128, 3);
    mma_gemm_qkv<<<gqkv, 256, GEMM_SMEM>>>(p_xn, p_sn, q_w, k_w, v_w, q_b, k_b, v_b, p_q, p_k, p_v);

    attn_kernel<<<BB*NH*16, 128, ATTN_SMEM>>>(p_q, p_k, p_v, age, mod_age, p_y);

    dim3 g768(NE/128, NT/128);
    mma_gemm<<<g768, 256, GEMM_SMEM>>>(p_y, c_w, c_b, x, p_x2, NE, NE, 0);
    ln_kernel<<<NT, 256>>>(p_x2, ln2_w, ln2_b, p_h1);

    dim3 g3072(4*NE/128, NT/128);
    mma_gemm<<<g3072, 256, GEMM_SMEM>>>(p_h1, fc_w, fc_b, nullptr, p_h2, 4*NE, NE, 3);
    mma_gemm<<<g768, 256, GEMM_SMEM>>>(p_h2, pj_w, pj_b, p_x2, out, NE, 4*NE, 0);
}

// round 8
// speedup vs baseline: 1.4393x; 1.4393x over previous
#include <cuda_runtime.h>
#include <stdint.h>
#include <math.h>

#define NE 768
#define LM 1024
#define LS 1024
#define BB 4
#define NH 12
#define HD 64
#define NT (BB*LM)

// ---------------- scratch ------------------------------------------------------
__device__ float g_sn[NT*NE];
__device__ float g_xn[NT*NE];
__device__ float g_q [NT*NE];
__device__ float g_k [NT*NE];
__device__ float g_v [NT*NE];
__device__ float g_y [NT*NE];
__device__ float g_x2[NT*NE];
__device__ float g_h1[NT*NE];
__device__ float g_h2[NT*4*NE];
__device__ int   g_code[NT];

__device__ __forceinline__ uint32_t f2tf32(float x) {
    uint32_t r;
    asm("cvt.rna.tf32.f32 %0, %1;" : "=r"(r) : "f"(x));
    return r;
}
__device__ __forceinline__ float roundtf(float x) { return __uint_as_float(f2tf32(x)); }

__device__ __forceinline__ void cp16(void* smem, const void* g) {
    uint32_t s = (uint32_t)__cvta_generic_to_shared(smem);
    asm volatile("cp.async.ca.shared.global [%0], [%1], 16;" :: "r"(s), "l"(g));
}

// ---------------- fuse_embed scan ----------------------------------------------
__global__ void scan_kernel(const int* __restrict__ mod_idx, int* __restrict__ code) {
    int b = blockIdx.x;
    __shared__ int s[LS];
    int t = threadIdx.x;
    int idx = mod_idx[b*LS + t];
    int is2 = (idx == 2) ? 1 : 0;
    s[t] = is2;
    __syncthreads();
    for (int off = 1; off < LS; off <<= 1) {
        int v = (t >= off) ? s[t - off] : 0;
        __syncthreads();
        s[t] += v;
        __syncthreads();
    }
    int c2 = s[t];
    int occ = is2 ? (c2 - 1) : (t + 1 - c2 - 1);
    if (occ < 0) occ = 0;
    if (occ > LS/2 - 1) occ = LS/2 - 1;
    code[b*LS + t] = ((b*(LS/2) + occ) << 1) | (is2 ? 0 : 1);
}

// ---------------- LayerNorm (outputs tf32-rounded) ------------------------------
__device__ __forceinline__ void ln_body(const float* __restrict__ p,
                                        const float* __restrict__ w,
                                        const float* __restrict__ bias,
                                        float* __restrict__ o) {
    int t = threadIdx.x;
    float v0 = p[t], v1 = p[t+256], v2 = p[t+512];
    float s = v0 + v1 + v2;
    float q = v0*v0 + v1*v1 + v2*v2;
    __shared__ float sb1[8], sb2[8];
    int lane = t & 31, wrp = t >> 5;
    #pragma unroll
    for (int o2 = 16; o2; o2 >>= 1) {
        s += __shfl_xor_sync(0xffffffffu, s, o2);
        q += __shfl_xor_sync(0xffffffffu, q, o2);
    }
    if (lane == 0) { sb1[wrp] = s; sb2[wrp] = q; }
    __syncthreads();
    if (t == 0) {
        float S = 0.f, Q = 0.f;
        #pragma unroll
        for (int i = 0; i < 8; i++) { S += sb1[i]; Q += sb2[i]; }
        sb1[0] = S; sb2[0] = Q;
    }
    __syncthreads();
    float mean = sb1[0] * (1.0f/NE);
    float var  = sb2[0] * (1.0f/NE) - mean*mean;
    float r = rsqrtf(var + 1e-5f);
    o[t]     = roundtf((v0 - mean) * r * w[t]     + bias[t]);
    o[t+256] = roundtf((v1 - mean) * r * w[t+256] + bias[t+256]);
    o[t+512] = roundtf((v2 - mean) * r * w[t+512] + bias[t+512]);
}

__global__ void ln_kernel(const float* __restrict__ in, const float* __restrict__ w,
                          const float* __restrict__ bias, float* __restrict__ out) {
    int row = blockIdx.x;
    ln_body(in + (size_t)row*NE, w, bias, out + (size_t)row*NE);
}

__global__ void gather_ln_kernel(const int* __restrict__ code,
                                 const float* __restrict__ m2, const float* __restrict__ m3,
                                 const float* __restrict__ w,  const float* __restrict__ bias,
                                 float* __restrict__ out) {
    int row = blockIdx.x;
    int c = code[row];
    const float* src = ((c & 1) ? m3 : m2) + (size_t)(c >> 1) * NE;
    ln_body(src, w, bias, out + (size_t)row*NE);
}

// ---------------- tf32 tensor-core GEMM (R4 config: BK16, static smem) ----------
#define BM 128
#define BN 128
#define BK 16
#define KSTRIDE (BK+4)

__device__ __forceinline__ void gemm_body(
    const float* A, const float* W, const float* bias, const float* res,
    float* C, int N, int K, int act)
{
    __shared__ float As[2][BM][KSTRIDE];
    __shared__ float Ws[2][BN][KSTRIDE];

    int tid = threadIdx.x, lane = tid & 31, warp = tid >> 5;
    int g = lane >> 2, c = lane & 3;
    int wm = (warp >> 2) * 64;
    int wn = (warp & 3) * 32;
    int bm = blockIdx.y * BM, bn = blockIdx.x * BN;

    float acc[4][4][4];
    #pragma unroll
    for (int mi = 0; mi < 4; mi++)
        #pragma unroll
        for (int ni = 0; ni < 4; ni++)
            #pragma unroll
            for (int r = 0; r < 4; r++) acc[mi][ni][r] = 0.f;

    const int nt = K / BK;

    #pragma unroll
    for (int i = 0; i < 2; i++) {
        int f = tid + i*256;
        int m = f >> 2, kk = (f & 3) << 2;
        cp16(&As[0][m][kk], A + (size_t)(bm+m)*K + kk);
        cp16(&Ws[0][m][kk], W + (size_t)(bn+m)*K + kk);
    }
    asm volatile("cp.async.commit_group;");

    for (int kt = 0; kt < nt; kt++) {
        int buf = kt & 1;
        if (kt + 1 < nt) {
            int k0 = (kt+1) * BK;
            #pragma unroll
            for (int i = 0; i < 2; i++) {
                int f = tid + i*256;
                int m = f >> 2, kk = (f & 3) << 2;
                cp16(&As[buf^1][m][kk], A + (size_t)(bm+m)*K + k0 + kk);
                cp16(&Ws[buf^1][m][kk], W + (size_t)(bn+m)*K + k0 + kk);
            }
            asm volatile("cp.async.commit_group;");
            asm volatile("cp.async.wait_group 1;");
        } else {
            asm volatile("cp.async.wait_group 0;");
        }
        __syncthreads();

        #pragma unroll
        for (int ks = 0; ks < BK; ks += 8) {
            uint32_t af[4][4], bf[4][2];
            #pragma unroll
            for (int mi = 0; mi < 4; mi++) {
                int r = wm + mi*16;
                af[mi][0] = __float_as_uint(As[buf][r+g   ][ks+c  ]);
                af[mi][1] = __float_as_uint(As[buf][r+g+8 ][ks+c  ]);
                af[mi][2] = __float_as_uint(As[buf][r+g   ][ks+c+4]);
                af[mi][3] = __float_as_uint(As[buf][r+g+8 ][ks+c+4]);
            }
            #pragma unroll
            for (int ni = 0; ni < 4; ni++) {
                int cn = wn + ni*8;
                bf[ni][0] = __float_as_uint(Ws[buf][cn+g][ks+c  ]);
                bf[ni][1] = __float_as_uint(Ws[buf][cn+g][ks+c+4]);
            }
            #pragma unroll
            for (int mi = 0; mi < 4; mi++)
                #pragma unroll
                for (int ni = 0; ni < 4; ni++) {
                    asm volatile(
                        "mma.sync.aligned.m16n8k8.row.col.f32.tf32.tf32.f32 "
                        "{%0,%1,%2,%3}, {%4,%5,%6,%7}, {%8,%9}, {%0,%1,%2,%3};"
                        : "+f"(acc[mi][ni][0]), "+f"(acc[mi][ni][1]),
                          "+f"(acc[mi][ni][2]), "+f"(acc[mi][ni][3])
                        : "r"(af[mi][0]), "r"(af[mi][1]), "r"(af[mi][2]), "r"(af[mi][3]),
                          "r"(bf[ni][0]), "r"(bf[ni][1]));
                }
        }
        __syncthreads();
    }

    #pragma unroll
    for (int mi = 0; mi < 4; mi++) {
        #pragma unroll
        for (int half = 0; half < 2; half++) {
            int gm = bm + wm + mi*16 + g + half*8;
            #pragma unroll
            for (int ni = 0; ni < 4; ni++) {
                int gn = bn + wn + ni*8 + c*2;
                float v0 = acc[mi][ni][half*2+0] + bias[gn];
                float v1 = acc[mi][ni][half*2+1] + bias[gn+1];
                if (res) {
                    const float2 r2 = *(const float2*)(res + (size_t)gm*N + gn);
                    v0 += r2.x; v1 += r2.y;
                }
                if (act & 1) {
                    v0 = 0.5f * v0 * (1.0f + erff(v0 * 0.70710678118654752f));
                    v1 = 0.5f * v1 * (1.0f + erff(v1 * 0.70710678118654752f));
                }
                if (act & 2) { v0 = roundtf(v0); v1 = roundtf(v1); }
                *(float2*)(C + (size_t)gm*N + gn) = make_float2(v0, v1);
            }
        }
    }
}

__global__ __launch_bounds__(256) void mma_gemm(
    const float* A, const float* W, const float* bias, const float* res,
    float* C, int N, int K, int act)
{
    gemm_body(A, W, bias, res, C, N, K, act);
}

__global__ __launch_bounds__(256) void mma_gemm_qkv(
    const float* xn, const float* sn,
    const float* wq, const float* wk, const float* wv,
    const float* qb, const float* kb, const float* vb,
    float* q, float* k, float* v)
{
    int z = blockIdx.z;
    const float* A = (z == 0) ? xn : sn;
    const float* W = (z == 0) ? wq : (z == 1) ? wk : wv;
    const float* B = (z == 0) ? qb : (z == 1) ? kb : vb;
    float*       C = (z == 0) ? q  : (z == 1) ? k  : v;
    gemm_body(A, W, B, nullptr, C, NE, NE, 2);
}

// ---------------- tensor-core flash attention, cp.async double-buffered --------
#define AP 68
#define ATTN_SMEM ((1024 + 64 + 6*64*AP) * 4)

__global__ __launch_bounds__(128) void attn_kernel(
    const float* __restrict__ Q, const float* __restrict__ Kg, const float* __restrict__ Vg,
    const float* __restrict__ age, const float* __restrict__ mod_age,
    float* __restrict__ Y)
{
    extern __shared__ float smn[];
    float* ma = smn;
    int*   km = (int*)(smn + 1024);
    float* Qs = smn + 1024 + 64;
    float* Ps = Qs + 64*AP;
    float* Kb = Ps + 64*AP;          // [2][64][AP]
    float* Vb = Kb + 2*64*AP;        // [2][64][AP]

    int blk = blockIdx.x;
    int qt   = blk & 15;
    int hd_i = (blk >> 4) % NH;
    int b    = blk / (16*NH);
    int tid  = threadIdx.x;
    int lane = tid & 31, warp = tid >> 5;
    int g = lane >> 2, c = lane & 3;
    int wr = warp * 16;

    for (int i = tid; i < LS; i += 128) ma[i] = mod_age[b*LS + i];
    __syncthreads();

    if (tid < 64) {
        float a = age[b*LM + qt*64 + tid];
        int lo = 0, hi = LS;
        while (lo < hi) { int mid = (lo+hi) >> 1; if (ma[mid] <= a) lo = mid+1; else hi = mid; }
        km[tid] = lo;
    }
    __syncthreads();
    int kmax_blk = 0;
    #pragma unroll 8
    for (int i = 0; i < 64; i++) kmax_blk = max(kmax_blk, km[i]);

    int tq = b*LM + qt*64;
    // Q tile: 64 rows x 64 floats = 1024 16B chunks (8 per thread)
    #pragma unroll
    for (int i = 0; i < 8; i++) {
        int f = tid + i*128;          // 0..1023
        int r = f >> 4, q4 = (f & 15) << 2;
        cp16(Qs + r*AP + q4, Q + (size_t)(tq+r)*NE + hd_i*HD + q4);
    }

    const size_t kvbase = (size_t)(b*LS)*NE + hd_i*HD;
    int ntile = (kmax_blk + 63) >> 6;

    // prefetch tile 0 (garbage beyond kmax masked arithmetically; all rows < LS)
    if (ntile > 0) {
        #pragma unroll
        for (int i = 0; i < 8; i++) {
            int f = tid + i*128;
            int r = f >> 4, q4 = (f & 15) << 2;
            cp16(Kb + r*AP + q4, Kg + kvbase + (size_t)r*NE + q4);
            cp16(Vb + r*AP + q4, Vg + kvbase + (size_t)r*NE + q4);
        }
    }
    asm volatile("cp.async.commit_group;");

    float m0 = -1e30f, m1 = -1e30f, l0 = 0.f, l1 = 0.f;
    float Oacc[8][4];
    #pragma unroll
    for (int ni = 0; ni < 8; ni++)
        #pragma unroll
        for (int r = 0; r < 4; r++) Oacc[ni][r] = 0.f;

    int km0 = km[wr + g];
    int km1 = km[wr + g + 8];

    for (int t = 0; t < ntile; t++) {
        int bf = t & 1;
        if (t + 1 < ntile) {
            int j1 = (t+1) * 64;
            int nb = bf ^ 1;
            #pragma unroll
            for (int i = 0; i < 8; i++) {
                int f = tid + i*128;
                int r = f >> 4, q4 = (f & 15) << 2;
                cp16(Kb + nb*64*AP + r*AP + q4, Kg + kvbase + (size_t)(j1+r)*NE + q4);
                cp16(Vb + nb*64*AP + r*AP + q4, Vg + kvbase + (size_t)(j1+r)*NE + q4);
            }
            asm volatile("cp.async.commit_group;");
            asm volatile("cp.async.wait_group 1;");
        } else {
            asm volatile("cp.async.wait_group 0;");
        }
        __syncthreads();

        const float* Ks = Kb + bf*64*AP;
        const float* Vs = Vb + bf*64*AP;
        int j0 = t * 64;

        float Sacc[8][4];
        #pragma unroll
        for (int ni = 0; ni < 8; ni++)
            #pragma unroll
            for (int r = 0; r < 4; r++) Sacc[ni][r] = 0.f;

        #pragma unroll
        for (int kk = 0; kk < 64; kk += 8) {
            uint32_t a0 = __float_as_uint(Qs[(wr+g  )*AP + kk + c  ]);
            uint32_t a1 = __float_as_uint(Qs[(wr+g+8)*AP + kk + c  ]);
            uint32_t a2 = __float_as_uint(Qs[(wr+g  )*AP + kk + c+4]);
            uint32_t a3 = __float_as_uint(Qs[(wr+g+8)*AP + kk + c+4]);
            #pragma unroll
            for (int ni = 0; ni < 8; ni++) {
                uint32_t b0 = __float_as_uint(Ks[(ni*8+g)*AP + kk + c  ]);
                uint32_t b1 = __float_as_uint(Ks[(ni*8+g)*AP + kk + c+4]);
                asm volatile(
                    "mma.sync.aligned.m16n8k8.row.col.f32.tf32.tf32.f32 "
                    "{%0,%1,%2,%3}, {%4,%5,%6,%7}, {%8,%9}, {%0,%1,%2,%3};"
                    : "+f"(Sacc[ni][0]), "+f"(Sacc[ni][1]), "+f"(Sacc[ni][2]), "+f"(Sacc[ni][3])
                    : "r"(a0), "r"(a1), "r"(a2), "r"(a3), "r"(b0), "r"(b1));
            }
        }

        #pragma unroll
        for (int hh = 0; hh < 2; hh++) {
            int row = wr + g + hh*8;
            int kmr = hh ? km1 : km0;
            float mold = hh ? m1 : m0;

            float mx = -1e30f;
            #pragma unroll
            for (int ni = 0; ni < 8; ni++) {
                int c0 = j0 + ni*8 + 2*c;
                float s0 = (c0   < kmr) ? Sacc[ni][hh*2  ] * 0.125f : -1e30f;
                float s1 = (c0+1 < kmr) ? Sacc[ni][hh*2+1] * 0.125f : -1e30f;
                Sacc[ni][hh*2] = s0; Sacc[ni][hh*2+1] = s1;
                mx = fmaxf(mx, fmaxf(s0, s1));
            }
            mx = fmaxf(mx, __shfl_xor_sync(0xffffffffu, mx, 1));
            mx = fmaxf(mx, __shfl_xor_sync(0xffffffffu, mx, 2));
            float mnew = fmaxf(mold, mx);
            float alpha = __expf(mold - mnew);

            float lsum = 0.f;
            #pragma unroll
            for (int ni = 0; ni < 8; ni++) {
                int c0 = j0 + ni*8 + 2*c;
                float p0 = (c0   < kmr) ? __expf(Sacc[ni][hh*2  ] - mnew) : 0.f;
                float p1 = (c0+1 < kmr) ? __expf(Sacc[ni][hh*2+1] - mnew) : 0.f;
                lsum += p0 + p1;
                *(float2*)(Ps + row*AP + ni*8 + 2*c) = make_float2(roundtf(p0), roundtf(p1));
            }
            lsum += __shfl_xor_sync(0xffffffffu, lsum, 1);
            lsum += __shfl_xor_sync(0xffffffffu, lsum, 2);

            if (hh) { l1 = l1*alpha + lsum; m1 = mnew; }
            else    { l0 = l0*alpha + lsum; m0 = mnew; }
            #pragma unroll
            for (int ni = 0; ni < 8; ni++) {
                Oacc[ni][hh*2  ] *= alpha;
                Oacc[ni][hh*2+1] *= alpha;
            }
        }
        __syncwarp();

        #pragma unroll
        for (int kk = 0; kk < 64; kk += 8) {
            uint32_t a0 = __float_as_uint(Ps[(wr+g  )*AP + kk + c  ]);
            uint32_t a1 = __float_as_uint(Ps[(wr+g+8)*AP + kk + c  ]);
            uint32_t a2 = __float_as_uint(Ps[(wr+g  )*AP + kk + c+4]);
            uint32_t a3 = __float_as_uint(Ps[(wr+g+8)*AP + kk + c+4]);
            #pragma unroll
            for (int ni = 0; ni < 8; ni++) {
                uint32_t b0 = __float_as_uint(Vs[(kk+c  )*AP + ni*8 + g]);
                uint32_t b1 = __float_as_uint(Vs[(kk+c+4)*AP + ni*8 + g]);
                asm volatile(
                    "mma.sync.aligned.m16n8k8.row.col.f32.tf32.tf32.f32 "
                    "{%0,%1,%2,%3}, {%4,%5,%6,%7}, {%8,%9}, {%0,%1,%2,%3};"
                    : "+f"(Oacc[ni][0]), "+f"(Oacc[ni][1]), "+f"(Oacc[ni][2]), "+f"(Oacc[ni][3])
                    : "r"(a0), "r"(a1), "r"(a2), "r"(a3), "r"(b0), "r"(b1));
            }
        }
        __syncthreads();
    }

    float inv0 = (l0 > 0.f) ? 1.0f / l0 : 0.f;
    float inv1 = (l1 > 0.f) ? 1.0f / l1 : 0.f;
    #pragma unroll
    for (int hh = 0; hh < 2; hh++) {
        int row = wr + g + hh*8;
        float inv = hh ? inv1 : inv0;
        float* yp = Y + (size_t)(tq + row)*NE + hd_i*HD;
        #pragma unroll
        for (int ni = 0; ni < 8; ni++) {
            float v0 = roundtf(Oacc[ni][hh*2  ] * inv);
            float v1 = roundtf(Oacc[ni][hh*2+1] * inv);
            *(float2*)(yp + ni*8 + 2*c) = make_float2(v0, v1);
        }
    }
}

// ---------------- launch -------------------------------------------------------
extern "C" void kernel_launch(void* const* d_in, const int* in_sizes, int n_in,
                              void* d_out, int out_size) {
    const float* x       = (const float*)d_in[0];
    const float* age     = (const float*)d_in[1];
    const int*   mod_idx = (const int*)  d_in[2];
    const float* mod_age = (const float*)d_in[3];
    const float* m2      = (const float*)d_in[4];
    const float* m3      = (const float*)d_in[5];
    const float* ln0_w = (const float*)d_in[6],  *ln0_b = (const float*)d_in[7];
    const float* ln1_w = (const float*)d_in[8],  *ln1_b = (const float*)d_in[9];
    const float* ln2_w = (const float*)d_in[10], *ln2_b = (const float*)d_in[11];
    const float* q_w  = (const float*)d_in[12], *q_b  = (const float*)d_in[13];
    const float* k_w  = (const float*)d_in[14], *k_b  = (const float*)d_in[15];
    const float* v_w  = (const float*)d_in[16], *v_b  = (const float*)d_in[17];
    const float* c_w  = (const float*)d_in[18], *c_b  = (const float*)d_in[19];
    const float* fc_w = (const float*)d_in[20], *fc_b = (const float*)d_in[21];
    const float* pj_w = (const float*)d_in[22], *pj_b = (const float*)d_in[23];
    float* out = (float*)d_out;

    float *p_sn,*p_xn,*p_q,*p_k,*p_v,*p_y,*p_x2,*p_h1,*p_h2;
    int *p_code;
    cudaGetSymbolAddress((void**)&p_sn,  g_sn);
    cudaGetSymbolAddress((void**)&p_xn,  g_xn);
    cudaGetSymbolAddress((void**)&p_q,   g_q);
    cudaGetSymbolAddress((void**)&p_k,   g_k);
    cudaGetSymbolAddress((void**)&p_v,   g_v);
    cudaGetSymbolAddress((void**)&p_y,   g_y);
    cudaGetSymbolAddress((void**)&p_x2,  g_x2);
    cudaGetSymbolAddress((void**)&p_h1,  g_h1);
    cudaGetSymbolAddress((void**)&p_h2,  g_h2);
    cudaGetSymbolAddress((void**)&p_code, g_code);

    static bool attr_set = false;
    if (!attr_set) {
        cudaFuncSetAttribute(attn_kernel, cudaFuncAttributeMaxDynamicSharedMemorySize, ATTN_SMEM);
        attr_set = true;
    }

    scan_kernel<<<BB, LS>>>(mod_idx, p_code);
    gather_ln_kernel<<<NT, 256>>>(p_code, m2, m3, ln0_w, ln0_b, p_sn);
    ln_kernel<<<NT, 256>>>(x, ln1_w, ln1_b, p_xn);

    dim3 gqkv(NE/128, NT/128, 3);
    mma_gemm_qkv<<<gqkv, 256>>>(p_xn, p_sn, q_w, k_w, v_w, q_b, k_b, v_b, p_q, p_k, p_v);

    attn_kernel<<<BB*NH*16, 128, ATTN_SMEM>>>(p_q, p_k, p_v, age, mod_age, p_y);

    dim3 g768(NE/128, NT/128);
    mma_gemm<<<g768, 256>>>(p_y, c_w, c_b, x, p_x2, NE, NE, 0);
    ln_kernel<<<NT, 256>>>(p_x2, ln2_w, ln2_b, p_h1);

    dim3 g3072(4*NE/128, NT/128);
    mma_gemm<<<g3072, 256>>>(p_h1, fc_w, fc_b, nullptr, p_h2, 4*NE, NE, 1);
    mma_gemm<<<g768, 256>>>(p_h2, pj_w, pj_b, p_x2, out, NE, 4*NE, 0);
}

// round 12
// speedup vs baseline: 1.5426x; 1.0718x over previous
#include <cuda_runtime.h>
#include <stdint.h>
#include <math.h>

#define NE 768
#define LM 1024
#define LS 1024
#define BB 4
#define NH 12
#define HD 64
#define NT (BB*LM)

// ---------------- scratch ------------------------------------------------------
__device__ float g_sn[NT*NE];
__device__ float g_xn[NT*NE];
__device__ float g_q [NT*NE];   // reused as split-K partial t1 after attention
__device__ float g_k [NT*NE];   // reused as split-K partial t2 after attention
__device__ float g_v [NT*NE];
__device__ float g_y [NT*NE];
__device__ float g_x2[NT*NE];
__device__ float g_h1[NT*NE];
__device__ float g_h2[NT*4*NE];
__device__ int   g_code[NT];

__device__ __forceinline__ uint32_t f2tf32(float x) {
    uint32_t r;
    asm("cvt.rna.tf32.f32 %0, %1;" : "=r"(r) : "f"(x));
    return r;
}
__device__ __forceinline__ float roundtf(float x) { return __uint_as_float(f2tf32(x)); }

__device__ __forceinline__ void cp16(void* smem, const void* g) {
    uint32_t s = (uint32_t)__cvta_generic_to_shared(smem);
    asm volatile("cp.async.ca.shared.global [%0], [%1], 16;" :: "r"(s), "l"(g));
}

// ---------------- fuse_embed scan ----------------------------------------------
__global__ void scan_kernel(const int* __restrict__ mod_idx, int* __restrict__ code) {
    int b = blockIdx.x;
    __shared__ int s[LS];
    int t = threadIdx.x;
    int idx = mod_idx[b*LS + t];
    int is2 = (idx == 2) ? 1 : 0;
    s[t] = is2;
    __syncthreads();
    for (int off = 1; off < LS; off <<= 1) {
        int v = (t >= off) ? s[t - off] : 0;
        __syncthreads();
        s[t] += v;
        __syncthreads();
    }
    int c2 = s[t];
    int occ = is2 ? (c2 - 1) : (t + 1 - c2 - 1);
    if (occ < 0) occ = 0;
    if (occ > LS/2 - 1) occ = LS/2 - 1;
    code[b*LS + t] = ((b*(LS/2) + occ) << 1) | (is2 ? 0 : 1);
}

// ---------------- LayerNorm (outputs tf32-rounded) ------------------------------
__device__ __forceinline__ void ln_body(const float* __restrict__ p,
                                        const float* __restrict__ w,
                                        const float* __restrict__ bias,
                                        float* __restrict__ o) {
    int t = threadIdx.x;
    float v0 = p[t], v1 = p[t+256], v2 = p[t+512];
    float s = v0 + v1 + v2;
    float q = v0*v0 + v1*v1 + v2*v2;
    __shared__ float sb1[8], sb2[8];
    int lane = t & 31, wrp = t >> 5;
    #pragma unroll
    for (int o2 = 16; o2; o2 >>= 1) {
        s += __shfl_xor_sync(0xffffffffu, s, o2);
        q += __shfl_xor_sync(0xffffffffu, q, o2);
    }
    if (lane == 0) { sb1[wrp] = s; sb2[wrp] = q; }
    __syncthreads();
    if (t == 0) {
        float S = 0.f, Q = 0.f;
        #pragma unroll
        for (int i = 0; i < 8; i++) { S += sb1[i]; Q += sb2[i]; }
        sb1[0] = S; sb2[0] = Q;
    }
    __syncthreads();
    float mean = sb1[0] * (1.0f/NE);
    float var  = sb2[0] * (1.0f/NE) - mean*mean;
    float r = rsqrtf(var + 1e-5f);
    o[t]     = roundtf((v0 - mean) * r * w[t]     + bias[t]);
    o[t+256] = roundtf((v1 - mean) * r * w[t+256] + bias[t+256]);
    o[t+512] = roundtf((v2 - mean) * r * w[t+512] + bias[t+512]);
}

__global__ void ln_kernel(const float* __restrict__ in, const float* __restrict__ w,
                          const float* __restrict__ bias, float* __restrict__ out) {
    int row = blockIdx.x;
    ln_body(in + (size_t)row*NE, w, bias, out + (size_t)row*NE);
}

// fused: blocks [0,NT) do gather+ln0 into sn; blocks [NT,2NT) do ln1(x) into xn
__global__ void ln_pair_kernel(const int* __restrict__ code,
                               const float* __restrict__ m2, const float* __restrict__ m3,
                               const float* __restrict__ ln0w, const float* __restrict__ ln0b,
                               const float* __restrict__ x,
                               const float* __restrict__ ln1w, const float* __restrict__ ln1b,
                               float* __restrict__ sn, float* __restrict__ xn) {
    int row = blockIdx.x;
    if (row < NT) {
        int c = code[row];
        const float* src = ((c & 1) ? m3 : m2) + (size_t)(c >> 1) * NE;
        ln_body(src, ln0w, ln0b, sn + (size_t)row*NE);
    } else {
        row -= NT;
        ln_body(x + (size_t)row*NE, ln1w, ln1b, xn + (size_t)row*NE);
    }
}

// ---------------- tf32 tensor-core GEMM (BK16, static smem) ---------------------
// Weights fed as raw fp32 bits (HMMA.tf32 truncates low 13 mantissa bits).
// act bit0 = gelu, bit1 = round output to tf32. bias==nullptr -> raw partials.
#define BM 128
#define BN 128
#define BK 16
#define KSTRIDE (BK+4)

__device__ __forceinline__ void gemm_body(
    const float* A, const float* W, const float* bias, const float* res,
    float* C, int N, int K, int lda, int koff, int act)
{
    __shared__ float As[2][BM][KSTRIDE];
    __shared__ float Ws[2][BN][KSTRIDE];

    int tid = threadIdx.x, lane = tid & 31, warp = tid >> 5;
    int g = lane >> 2, c = lane & 3;
    int wm = (warp >> 2) * 64;
    int wn = (warp & 3) * 32;
    int bm = blockIdx.y * BM, bn = blockIdx.x * BN;

    float acc[4][4][4];
    #pragma unroll
    for (int mi = 0; mi < 4; mi++)
        #pragma unroll
        for (int ni = 0; ni < 4; ni++)
            #pragma unroll
            for (int r = 0; r < 4; r++) acc[mi][ni][r] = 0.f;

    const int nt = K / BK;

    #pragma unroll
    for (int i = 0; i < 2; i++) {
        int f = tid + i*256;
        int m = f >> 2, kk = (f & 3) << 2;
        cp16(&As[0][m][kk], A + (size_t)(bm+m)*lda + koff + kk);
        cp16(&Ws[0][m][kk], W + (size_t)(bn+m)*lda + koff + kk);
    }
    asm volatile("cp.async.commit_group;");

    for (int kt = 0; kt < nt; kt++) {
        int buf = kt & 1;
        if (kt + 1 < nt) {
            int k0 = koff + (kt+1) * BK;
            #pragma unroll
            for (int i = 0; i < 2; i++) {
                int f = tid + i*256;
                int m = f >> 2, kk = (f & 3) << 2;
                cp16(&As[buf^1][m][kk], A + (size_t)(bm+m)*lda + k0 + kk);
                cp16(&Ws[buf^1][m][kk], W + (size_t)(bn+m)*lda + k0 + kk);
            }
            asm volatile("cp.async.commit_group;");
            asm volatile("cp.async.wait_group 1;");
        } else {
            asm volatile("cp.async.wait_group 0;");
        }
        __syncthreads();

        #pragma unroll
        for (int ks = 0; ks < BK; ks += 8) {
            uint32_t af[4][4], bf[4][2];
            #pragma unroll
            for (int mi = 0; mi < 4; mi++) {
                int r = wm + mi*16;
                af[mi][0] = __float_as_uint(As[buf][r+g   ][ks+c  ]);
                af[mi][1] = __float_as_uint(As[buf][r+g+8 ][ks+c  ]);
                af[mi][2] = __float_as_uint(As[buf][r+g   ][ks+c+4]);
                af[mi][3] = __float_as_uint(As[buf][r+g+8 ][ks+c+4]);
            }
            #pragma unroll
            for (int ni = 0; ni < 4; ni++) {
                int cn = wn + ni*8;
                bf[ni][0] = __float_as_uint(Ws[buf][cn+g][ks+c  ]);
                bf[ni][1] = __float_as_uint(Ws[buf][cn+g][ks+c+4]);
            }
            #pragma unroll
            for (int mi = 0; mi < 4; mi++)
                #pragma unroll
                for (int ni = 0; ni < 4; ni++) {
                    asm volatile(
                        "mma.sync.aligned.m16n8k8.row.col.f32.tf32.tf32.f32 "
                        "{%0,%1,%2,%3}, {%4,%5,%6,%7}, {%8,%9}, {%0,%1,%2,%3};"
                        : "+f"(acc[mi][ni][0]), "+f"(acc[mi][ni][1]),
                          "+f"(acc[mi][ni][2]), "+f"(acc[mi][ni][3])
                        : "r"(af[mi][0]), "r"(af[mi][1]), "r"(af[mi][2]), "r"(af[mi][3]),
                          "r"(bf[ni][0]), "r"(bf[ni][1]));
                }
        }
        __syncthreads();
    }

    #pragma unroll
    for (int mi = 0; mi < 4; mi++) {
        #pragma unroll
        for (int half = 0; half < 2; half++) {
            int gm = bm + wm + mi*16 + g + half*8;
            #pragma unroll
            for (int ni = 0; ni < 4; ni++) {
                int gn = bn + wn + ni*8 + c*2;
                float v0 = acc[mi][ni][half*2+0];
                float v1 = acc[mi][ni][half*2+1];
                if (bias) { v0 += bias[gn]; v1 += bias[gn+1]; }
                if (res) {
                    const float2 r2 = *(const float2*)(res + (size_t)gm*N + gn);
                    v0 += r2.x; v1 += r2.y;
                }
                if (act & 1) {
                    v0 = 0.5f * v0 * (1.0f + erff(v0 * 0.70710678118654752f));
                    v1 = 0.5f * v1 * (1.0f + erff(v1 * 0.70710678118654752f));
                }
                if (act & 2) { v0 = roundtf(v0); v1 = roundtf(v1); }
                *(float2*)(C + (size_t)gm*N + gn) = make_float2(v0, v1);
            }
        }
    }
}

__global__ __launch_bounds__(256) void mma_gemm(
    const float* A, const float* W, const float* bias, const float* res,
    float* C, int N, int K, int act)
{
    gemm_body(A, W, bias, res, C, N, K, K, 0, act);
}

__global__ __launch_bounds__(256) void mma_gemm_qkv(
    const float* xn, const float* sn,
    const float* wq, const float* wk, const float* wv,
    const float* qb, const float* kb, const float* vb,
    float* q, float* k, float* v)
{
    int z = blockIdx.z;
    const float* A = (z == 0) ? xn : sn;
    const float* W = (z == 0) ? wq : (z == 1) ? wk : wv;
    const float* B = (z == 0) ? qb : (z == 1) ? kb : vb;
    float*       C = (z == 0) ? q  : (z == 1) ? k  : v;
    gemm_body(A, W, B, nullptr, C, NE, NE, NE, 0, 2);
}

// split-K (z in {0,1}): each half writes raw partials (no bias/res/act)
__global__ __launch_bounds__(256) void mma_gemm_splitk(
    const float* A, const float* W, float* t1, float* t2,
    int N, int Khalf, int lda)
{
    int z = blockIdx.z;
    gemm_body(A, W, nullptr, nullptr, z ? t2 : t1, N, Khalf, lda, z * Khalf, 0);
}

// out = t1 + t2 + res + bias  (vectorized)
__global__ __launch_bounds__(256) void addsplit_kernel(
    const float4* __restrict__ t1, const float4* __restrict__ t2,
    const float4* __restrict__ res, const float* __restrict__ bias,
    float4* __restrict__ out, int n4, int N4)
{
    int i = blockIdx.x * blockDim.x + threadIdx.x;
    if (i >= n4) return;
    const float4* b4 = (const float4*)bias;
    float4 bb = b4[i % N4];
    float4 a = t1[i], b = t2[i], r = res[i];
    float4 o;
    o.x = a.x + b.x + r.x + bb.x;
    o.y = a.y + b.y + r.y + bb.y;
    o.z = a.z + b.z + r.z + bb.z;
    o.w = a.w + b.w + r.w + bb.w;
    out[i] = o;
}

// ---------------- tensor-core flash attention (R8, unchanged) -------------------
#define AP 68
#define ATTN_SMEM ((1024 + 64 + 6*64*AP) * 4)

__global__ __launch_bounds__(128) void attn_kernel(
    const float* __restrict__ Q, const float* __restrict__ Kg, const float* __restrict__ Vg,
    const float* __restrict__ age, const float* __restrict__ mod_age,
    float* __restrict__ Y)
{
    extern __shared__ float smn[];
    float* ma = smn;
    int*   km = (int*)(smn + 1024);
    float* Qs = smn + 1024 + 64;
    float* Ps = Qs + 64*AP;
    float* Kb = Ps + 64*AP;
    float* Vb = Kb + 2*64*AP;

    int blk = blockIdx.x;
    int qt   = blk & 15;
    int hd_i = (blk >> 4) % NH;
    int b    = blk / (16*NH);
    int tid  = threadIdx.x;
    int lane = tid & 31, warp = tid >> 5;
    int g = lane >> 2, c = lane & 3;
    int wr = warp * 16;

    for (int i = tid; i < LS; i += 128) ma[i] = mod_age[b*LS + i];
    __syncthreads();

    if (tid < 64) {
        float a = age[b*LM + qt*64 + tid];
        int lo = 0, hi = LS;
        while (lo < hi) { int mid = (lo+hi) >> 1; if (ma[mid] <= a) lo = mid+1; else hi = mid; }
        km[tid] = lo;
    }
    __syncthreads();
    int kmax_blk = 0;
    #pragma unroll 8
    for (int i = 0; i < 64; i++) kmax_blk = max(kmax_blk, km[i]);

    int tq = b*LM + qt*64;
    #pragma unroll
    for (int i = 0; i < 8; i++) {
        int f = tid + i*128;
        int r = f >> 4, q4 = (f & 15) << 2;
        cp16(Qs + r*AP + q4, Q + (size_t)(tq+r)*NE + hd_i*HD + q4);
    }

    const size_t kvbase = (size_t)(b*LS)*NE + hd_i*HD;
    int ntile = (kmax_blk + 63) >> 6;

    if (ntile > 0) {
        #pragma unroll
        for (int i = 0; i < 8; i++) {
            int f = tid + i*128;
            int r = f >> 4, q4 = (f & 15) << 2;
            cp16(Kb + r*AP + q4, Kg + kvbase + (size_t)r*NE + q4);
            cp16(Vb + r*AP + q4, Vg + kvbase + (size_t)r*NE + q4);
        }
    }
    asm volatile("cp.async.commit_group;");

    float m0 = -1e30f, m1 = -1e30f, l0 = 0.f, l1 = 0.f;
    float Oacc[8][4];
    #pragma unroll
    for (int ni = 0; ni < 8; ni++)
        #pragma unroll
        for (int r = 0; r < 4; r++) Oacc[ni][r] = 0.f;

    int km0 = km[wr + g];
    int km1 = km[wr + g + 8];

    for (int t = 0; t < ntile; t++) {
        int bf = t & 1;
        if (t + 1 < ntile) {
            int j1 = (t+1) * 64;
            int nb = bf ^ 1;
            #pragma unroll
            for (int i = 0; i < 8; i++) {
                int f = tid + i*128;
                int r = f >> 4, q4 = (f & 15) << 2;
                cp16(Kb + nb*64*AP + r*AP + q4, Kg + kvbase + (size_t)(j1+r)*NE + q4);
                cp16(Vb + nb*64*AP + r*AP + q4, Vg + kvbase + (size_t)(j1+r)*NE + q4);
            }
            asm volatile("cp.async.commit_group;");
            asm volatile("cp.async.wait_group 1;");
        } else {
            asm volatile("cp.async.wait_group 0;");
        }
        __syncthreads();

        const float* Ks = Kb + bf*64*AP;
        const float* Vs = Vb + bf*64*AP;
        int j0 = t * 64;

        float Sacc[8][4];
        #pragma unroll
        for (int ni = 0; ni < 8; ni++)
            #pragma unroll
            for (int r = 0; r < 4; r++) Sacc[ni][r] = 0.f;

        #pragma unroll
        for (int kk = 0; kk < 64; kk += 8) {
            uint32_t a0 = __float_as_uint(Qs[(wr+g  )*AP + kk + c  ]);
            uint32_t a1 = __float_as_uint(Qs[(wr+g+8)*AP + kk + c  ]);
            uint32_t a2 = __float_as_uint(Qs[(wr+g  )*AP + kk + c+4]);
            uint32_t a3 = __float_as_uint(Qs[(wr+g+8)*AP + kk + c+4]);
            #pragma unroll
            for (int ni = 0; ni < 8; ni++) {
                uint32_t b0 = __float_as_uint(Ks[(ni*8+g)*AP + kk + c  ]);
                uint32_t b1 = __float_as_uint(Ks[(ni*8+g)*AP + kk + c+4]);
                asm volatile(
                    "mma.sync.aligned.m16n8k8.row.col.f32.tf32.tf32.f32 "
                    "{%0,%1,%2,%3}, {%4,%5,%6,%7}, {%8,%9}, {%0,%1,%2,%3};"
                    : "+f"(Sacc[ni][0]), "+f"(Sacc[ni][1]), "+f"(Sacc[ni][2]), "+f"(Sacc[ni][3])
                    : "r"(a0), "r"(a1), "r"(a2), "r"(a3), "r"(b0), "r"(b1));
            }
        }

        #pragma unroll
        for (int hh = 0; hh < 2; hh++) {
            int row = wr + g + hh*8;
            int kmr = hh ? km1 : km0;
            float mold = hh ? m1 : m0;

            float mx = -1e30f;
            #pragma unroll
            for (int ni = 0; ni < 8; ni++) {
                int c0 = j0 + ni*8 + 2*c;
                float s0 = (c0   < kmr) ? Sacc[ni][hh*2  ] * 0.125f : -1e30f;
                float s1 = (c0+1 < kmr) ? Sacc[ni][hh*2+1] * 0.125f : -1e30f;
                Sacc[ni][hh*2] = s0; Sacc[ni][hh*2+1] = s1;
                mx = fmaxf(mx, fmaxf(s0, s1));
            }
            mx = fmaxf(mx, __shfl_xor_sync(0xffffffffu, mx, 1));
            mx = fmaxf(mx, __shfl_xor_sync(0xffffffffu, mx, 2));
            float mnew = fmaxf(mold, mx);
            float alpha = __expf(mold - mnew);

            float lsum = 0.f;
            #pragma unroll
            for (int ni = 0; ni < 8; ni++) {
                int c0 = j0 + ni*8 + 2*c;
                float p0 = (c0   < kmr) ? __expf(Sacc[ni][hh*2  ] - mnew) : 0.f;
                float p1 = (c0+1 < kmr) ? __expf(Sacc[ni][hh*2+1] - mnew) : 0.f;
                lsum += p0 + p1;
                *(float2*)(Ps + row*AP + ni*8 + 2*c) = make_float2(roundtf(p0), roundtf(p1));
            }
            lsum += __shfl_xor_sync(0xffffffffu, lsum, 1);
            lsum += __shfl_xor_sync(0xffffffffu, lsum, 2);

            if (hh) { l1 = l1*alpha + lsum; m1 = mnew; }
            else    { l0 = l0*alpha + lsum; m0 = mnew; }
            #pragma unroll
            for (int ni = 0; ni < 8; ni++) {
                Oacc[ni][hh*2  ] *= alpha;
                Oacc[ni][hh*2+1] *= alpha;
            }
        }
        __syncwarp();

        #pragma unroll
        for (int kk = 0; kk < 64; kk += 8) {
            uint32_t a0 = __float_as_uint(Ps[(wr+g  )*AP + kk + c  ]);
            uint32_t a1 = __float_as_uint(Ps[(wr+g+8)*AP + kk + c  ]);
            uint32_t a2 = __float_as_uint(Ps[(wr+g  )*AP + kk + c+4]);
            uint32_t a3 = __float_as_uint(Ps[(wr+g+8)*AP + kk + c+4]);
            #pragma unroll
            for (int ni = 0; ni < 8; ni++) {
                uint32_t b0 = __float_as_uint(Vs[(kk+c  )*AP + ni*8 + g]);
                uint32_t b1 = __float_as_uint(Vs[(kk+c+4)*AP + ni*8 + g]);
                asm volatile(
                    "mma.sync.aligned.m16n8k8.row.col.f32.tf32.tf32.f32 "
                    "{%0,%1,%2,%3}, {%4,%5,%6,%7}, {%8,%9}, {%0,%1,%2,%3};"
                    : "+f"(Oacc[ni][0]), "+f"(Oacc[ni][1]), "+f"(Oacc[ni][2]), "+f"(Oacc[ni][3])
                    : "r"(a0), "r"(a1), "r"(a2), "r"(a3), "r"(b0), "r"(b1));
            }
        }
        __syncthreads();
    }

    float inv0 = (l0 > 0.f) ? 1.0f / l0 : 0.f;
    float inv1 = (l1 > 0.f) ? 1.0f / l1 : 0.f;
    #pragma unroll
    for (int hh = 0; hh < 2; hh++) {
        int row = wr + g + hh*8;
        float inv = hh ? inv1 : inv0;
        float* yp = Y + (size_t)(tq + row)*NE + hd_i*HD;
        #pragma unroll
        for (int ni = 0; ni < 8; ni++) {
            float v0 = roundtf(Oacc[ni][hh*2  ] * inv);
            float v1 = roundtf(Oacc[ni][hh*2+1] * inv);
            *(float2*)(yp + ni*8 + 2*c) = make_float2(v0, v1);
        }
    }
}

// ---------------- launch -------------------------------------------------------
extern "C" void kernel_launch(void* const* d_in, const int* in_sizes, int n_in,
                              void* d_out, int out_size) {
    const float* x       = (const float*)d_in[0];
    const float* age     = (const float*)d_in[1];
    const int*   mod_idx = (const int*)  d_in[2];
    const float* mod_age = (const float*)d_in[3];
    const float* m2      = (const float*)d_in[4];
    const float* m3      = (const float*)d_in[5];
    const float* ln0_w = (const float*)d_in[6],  *ln0_b = (const float*)d_in[7];
    const float* ln1_w = (const float*)d_in[8],  *ln1_b = (const float*)d_in[9];
    const float* ln2_w = (const float*)d_in[10], *ln2_b = (const float*)d_in[11];
    const float* q_w  = (const float*)d_in[12], *q_b  = (const float*)d_in[13];
    const float* k_w  = (const float*)d_in[14], *k_b  = (const float*)d_in[15];
    const float* v_w  = (const float*)d_in[16], *v_b  = (const float*)d_in[17];
    const float* c_w  = (const float*)d_in[18], *c_b  = (const float*)d_in[19];
    const float* fc_w = (const float*)d_in[20], *fc_b = (const float*)d_in[21];
    const float* pj_w = (const float*)d_in[22], *pj_b = (const float*)d_in[23];
    float* out = (float*)d_out;

    float *p_sn,*p_xn,*p_q,*p_k,*p_v,*p_y,*p_x2,*p_h1,*p_h2;
    int *p_code;
    cudaGetSymbolAddress((void**)&p_sn,  g_sn);
    cudaGetSymbolAddress((void**)&p_xn,  g_xn);
    cudaGetSymbolAddress((void**)&p_q,   g_q);
    cudaGetSymbolAddress((void**)&p_k,   g_k);
    cudaGetSymbolAddress((void**)&p_v,   g_v);
    cudaGetSymbolAddress((void**)&p_y,   g_y);
    cudaGetSymbolAddress((void**)&p_x2,  g_x2);
    cudaGetSymbolAddress((void**)&p_h1,  g_h1);
    cudaGetSymbolAddress((void**)&p_h2,  g_h2);
    cudaGetSymbolAddress((void**)&p_code, g_code);

    static bool attr_set = false;
    if (!attr_set) {
        cudaFuncSetAttribute(attn_kernel, cudaFuncAttributeMaxDynamicSharedMemorySize, ATTN_SMEM);
        attr_set = true;
    }

    scan_kernel<<<BB, LS>>>(mod_idx, p_code);
    ln_pair_kernel<<<2*NT, 256>>>(p_code, m2, m3, ln0_w, ln0_b, x, ln1_w, ln1_b, p_sn, p_xn);

    dim3 gqkv(NE/128, NT/128, 3);
    mma_gemm_qkv<<<gqkv, 256>>>(p_xn, p_sn, q_w, k_w, v_w, q_b, k_b, v_b, p_q, p_k, p_v);

    attn_kernel<<<BB*NH*16, 128, ATTN_SMEM>>>(p_q, p_k, p_v, age, mod_age, p_y);

    dim3 g768(NE/128, NT/128);
    mma_gemm<<<g768, 256>>>(p_y, c_w, c_b, x, p_x2, NE, NE, 0);
    ln_kernel<<<NT, 256>>>(p_x2, ln2_w, ln2_b, p_h1);

    dim3 g3072(4*NE/128, NT/128);
    mma_gemm<<<g3072, 256>>>(p_h1, fc_w, fc_b, nullptr, p_h2, 4*NE, NE, 1);

    // proj: split-K2 (z=0: K[0,1536) -> t1(g_q), z=1: K[1536,3072) -> t2(g_k))
    dim3 gproj(NE/128, NT/128, 2);
    mma_gemm_splitk<<<gproj, 256>>>(p_h2, pj_w, p_q, p_k, NE, 2*NE, 4*NE);
    int n4 = NT*NE/4;
    addsplit_kernel<<<(n4 + 255)/256, 256>>>((const float4*)p_q, (const float4*)p_k,
                                             (const float4*)p_x2, pj_b,
                                             (float4*)out, n4, NE/4);
}

// round 13
// speedup vs baseline: 1.5479x; 1.0034x over previous
#include <cuda_runtime.h>
#include <stdint.h>
#include <math.h>

#define NE 768
#define LM 1024
#define LS 1024
#define BB 4
#define NH 12
#define HD 64
#define NT (BB*LM)

// ---------------- scratch ------------------------------------------------------
__device__ float g_sn[NT*NE];
__device__ float g_xn[NT*NE];
__device__ float g_q [NT*NE];   // reused as split-K partial t1 after attention
__device__ float g_k [NT*NE];   // reused as split-K partial t2 after attention
__device__ float g_v [NT*NE];
__device__ float g_y [NT*NE];
__device__ float g_x2[NT*NE];
__device__ float g_h1[NT*NE];
__device__ float g_h2[NT*4*NE];
__device__ int   g_code[NT];

__device__ __forceinline__ uint32_t f2tf32(float x) {
    uint32_t r;
    asm("cvt.rna.tf32.f32 %0, %1;" : "=r"(r) : "f"(x));
    return r;
}
__device__ __forceinline__ float roundtf(float x) { return __uint_as_float(f2tf32(x)); }

__device__ __forceinline__ void cp16(void* smem, const void* g) {
    uint32_t s = (uint32_t)__cvta_generic_to_shared(smem);
    asm volatile("cp.async.ca.shared.global [%0], [%1], 16;" :: "r"(s), "l"(g));
}

// ---------------- fuse_embed scan ----------------------------------------------
__global__ void scan_kernel(const int* __restrict__ mod_idx, int* __restrict__ code) {
    int b = blockIdx.x;
    __shared__ int s[LS];
    int t = threadIdx.x;
    int idx = mod_idx[b*LS + t];
    int is2 = (idx == 2) ? 1 : 0;
    s[t] = is2;
    __syncthreads();
    for (int off = 1; off < LS; off <<= 1) {
        int v = (t >= off) ? s[t - off] : 0;
        __syncthreads();
        s[t] += v;
        __syncthreads();
    }
    int c2 = s[t];
    int occ = is2 ? (c2 - 1) : (t + 1 - c2 - 1);
    if (occ < 0) occ = 0;
    if (occ > LS/2 - 1) occ = LS/2 - 1;
    code[b*LS + t] = ((b*(LS/2) + occ) << 1) | (is2 ? 0 : 1);
}

// ---------------- LayerNorm (outputs tf32-rounded) ------------------------------
__device__ __forceinline__ void ln_body(const float* __restrict__ p,
                                        const float* __restrict__ w,
                                        const float* __restrict__ bias,
                                        float* __restrict__ o) {
    int t = threadIdx.x;
    float v0 = p[t], v1 = p[t+256], v2 = p[t+512];
    float s = v0 + v1 + v2;
    float q = v0*v0 + v1*v1 + v2*v2;
    __shared__ float sb1[8], sb2[8];
    int lane = t & 31, wrp = t >> 5;
    #pragma unroll
    for (int o2 = 16; o2; o2 >>= 1) {
        s += __shfl_xor_sync(0xffffffffu, s, o2);
        q += __shfl_xor_sync(0xffffffffu, q, o2);
    }
    if (lane == 0) { sb1[wrp] = s; sb2[wrp] = q; }
    __syncthreads();
    if (t == 0) {
        float S = 0.f, Q = 0.f;
        #pragma unroll
        for (int i = 0; i < 8; i++) { S += sb1[i]; Q += sb2[i]; }
        sb1[0] = S; sb2[0] = Q;
    }
    __syncthreads();
    float mean = sb1[0] * (1.0f/NE);
    float var  = sb2[0] * (1.0f/NE) - mean*mean;
    float r = rsqrtf(var + 1e-5f);
    o[t]     = roundtf((v0 - mean) * r * w[t]     + bias[t]);
    o[t+256] = roundtf((v1 - mean) * r * w[t+256] + bias[t+256]);
    o[t+512] = roundtf((v2 - mean) * r * w[t+512] + bias[t+512]);
}

__global__ void ln_kernel(const float* __restrict__ in, const float* __restrict__ w,
                          const float* __restrict__ bias, float* __restrict__ out) {
    int row = blockIdx.x;
    ln_body(in + (size_t)row*NE, w, bias, out + (size_t)row*NE);
}

__global__ void ln_pair_kernel(const int* __restrict__ code,
                               const float* __restrict__ m2, const float* __restrict__ m3,
                               const float* __restrict__ ln0w, const float* __restrict__ ln0b,
                               const float* __restrict__ x,
                               const float* __restrict__ ln1w, const float* __restrict__ ln1b,
                               float* __restrict__ sn, float* __restrict__ xn) {
    int row = blockIdx.x;
    if (row < NT) {
        int c = code[row];
        const float* src = ((c & 1) ? m3 : m2) + (size_t)(c >> 1) * NE;
        ln_body(src, ln0w, ln0b, sn + (size_t)row*NE);
    } else {
        row -= NT;
        ln_body(x + (size_t)row*NE, ln1w, ln1b, xn + (size_t)row*NE);
    }
}

// ---------------- tf32 tensor-core GEMM (BK16, static smem) ---------------------
#define BM 128
#define BN 128
#define BK 16
#define KSTRIDE (BK+4)

__device__ __forceinline__ void gemm_body(
    const float* A, const float* W, const float* bias, const float* res,
    float* C, int N, int K, int lda, int koff, int act)
{
    __shared__ float As[2][BM][KSTRIDE];
    __shared__ float Ws[2][BN][KSTRIDE];

    int tid = threadIdx.x, lane = tid & 31, warp = tid >> 5;
    int g = lane >> 2, c = lane & 3;
    int wm = (warp >> 2) * 64;
    int wn = (warp & 3) * 32;
    int bm = blockIdx.y * BM, bn = blockIdx.x * BN;

    float acc[4][4][4];
    #pragma unroll
    for (int mi = 0; mi < 4; mi++)
        #pragma unroll
        for (int ni = 0; ni < 4; ni++)
            #pragma unroll
            for (int r = 0; r < 4; r++) acc[mi][ni][r] = 0.f;

    const int nt = K / BK;

    #pragma unroll
    for (int i = 0; i < 2; i++) {
        int f = tid + i*256;
        int m = f >> 2, kk = (f & 3) << 2;
        cp16(&As[0][m][kk], A + (size_t)(bm+m)*lda + koff + kk);
        cp16(&Ws[0][m][kk], W + (size_t)(bn+m)*lda + koff + kk);
    }
    asm volatile("cp.async.commit_group;");

    for (int kt = 0; kt < nt; kt++) {
        int buf = kt & 1;
        if (kt + 1 < nt) {
            int k0 = koff + (kt+1) * BK;
            #pragma unroll
            for (int i = 0; i < 2; i++) {
                int f = tid + i*256;
                int m = f >> 2, kk = (f & 3) << 2;
                cp16(&As[buf^1][m][kk], A + (size_t)(bm+m)*lda + k0 + kk);
                cp16(&Ws[buf^1][m][kk], W + (size_t)(bn+m)*lda + k0 + kk);
            }
            asm volatile("cp.async.commit_group;");
            asm volatile("cp.async.wait_group 1;");
        } else {
            asm volatile("cp.async.wait_group 0;");
        }
        __syncthreads();

        #pragma unroll
        for (int ks = 0; ks < BK; ks += 8) {
            uint32_t af[4][4], bf[4][2];
            #pragma unroll
            for (int mi = 0; mi < 4; mi++) {
                int r = wm + mi*16;
                af[mi][0] = __float_as_uint(As[buf][r+g   ][ks+c  ]);
                af[mi][1] = __float_as_uint(As[buf][r+g+8 ][ks+c  ]);
                af[mi][2] = __float_as_uint(As[buf][r+g   ][ks+c+4]);
                af[mi][3] = __float_as_uint(As[buf][r+g+8 ][ks+c+4]);
            }
            #pragma unroll
            for (int ni = 0; ni < 4; ni++) {
                int cn = wn + ni*8;
                bf[ni][0] = __float_as_uint(Ws[buf][cn+g][ks+c  ]);
                bf[ni][1] = __float_as_uint(Ws[buf][cn+g][ks+c+4]);
            }
            #pragma unroll
            for (int mi = 0; mi < 4; mi++)
                #pragma unroll
                for (int ni = 0; ni < 4; ni++) {
                    asm volatile(
                        "mma.sync.aligned.m16n8k8.row.col.f32.tf32.tf32.f32 "
                        "{%0,%1,%2,%3}, {%4,%5,%6,%7}, {%8,%9}, {%0,%1,%2,%3};"
                        : "+f"(acc[mi][ni][0]), "+f"(acc[mi][ni][1]),
                          "+f"(acc[mi][ni][2]), "+f"(acc[mi][ni][3])
                        : "r"(af[mi][0]), "r"(af[mi][1]), "r"(af[mi][2]), "r"(af[mi][3]),
                          "r"(bf[ni][0]), "r"(bf[ni][1]));
                }
        }
        __syncthreads();
    }

    #pragma unroll
    for (int mi = 0; mi < 4; mi++) {
        #pragma unroll
        for (int half = 0; half < 2; half++) {
            int gm = bm + wm + mi*16 + g + half*8;
            #pragma unroll
            for (int ni = 0; ni < 4; ni++) {
                int gn = bn + wn + ni*8 + c*2;
                float v0 = acc[mi][ni][half*2+0];
                float v1 = acc[mi][ni][half*2+1];
                if (bias) { v0 += bias[gn]; v1 += bias[gn+1]; }
                if (res) {
                    const float2 r2 = *(const float2*)(res + (size_t)gm*N + gn);
                    v0 += r2.x; v1 += r2.y;
                }
                if (act & 1) {
                    v0 = 0.5f * v0 * (1.0f + erff(v0 * 0.70710678118654752f));
                    v1 = 0.5f * v1 * (1.0f + erff(v1 * 0.70710678118654752f));
                }
                if (act & 2) { v0 = roundtf(v0); v1 = roundtf(v1); }
                *(float2*)(C + (size_t)gm*N + gn) = make_float2(v0, v1);
            }
        }
    }
}

__global__ __launch_bounds__(256) void mma_gemm(
    const float* A, const float* W, const float* bias, const float* res,
    float* C, int N, int K, int act)
{
    gemm_body(A, W, bias, res, C, N, K, K, 0, act);
}

__global__ __launch_bounds__(256) void mma_gemm_qkv(
    const float* xn, const float* sn,
    const float* wq, const float* wk, const float* wv,
    const float* qb, const float* kb, const float* vb,
    float* q, float* k, float* v)
{
    int z = blockIdx.z;
    const float* A = (z == 0) ? xn : sn;
    const float* W = (z == 0) ? wq : (z == 1) ? wk : wv;
    const float* B = (z == 0) ? qb : (z == 1) ? kb : vb;
    float*       C = (z == 0) ? q  : (z == 1) ? k  : v;
    gemm_body(A, W, B, nullptr, C, NE, NE, NE, 0, 2);
}

__global__ __launch_bounds__(256) void mma_gemm_splitk(
    const float* A, const float* W, float* t1, float* t2,
    int N, int Khalf, int lda)
{
    int z = blockIdx.z;
    gemm_body(A, W, nullptr, nullptr, z ? t2 : t1, N, Khalf, lda, z * Khalf, 0);
}

__global__ __launch_bounds__(256) void addsplit_kernel(
    const float4* __restrict__ t1, const float4* __restrict__ t2,
    const float4* __restrict__ res, const float* __restrict__ bias,
    float4* __restrict__ out, int n4, int N4)
{
    int i = blockIdx.x * blockDim.x + threadIdx.x;
    if (i >= n4) return;
    const float4* b4 = (const float4*)bias;
    float4 bb = b4[i % N4];
    float4 a = t1[i], b = t2[i], r = res[i];
    float4 o;
    o.x = a.x + b.x + r.x + bb.x;
    o.y = a.y + b.y + r.y + bb.y;
    o.z = a.z + b.z + r.z + bb.z;
    o.w = a.w + b.w + r.w + bb.w;
    out[i] = o;
}

// ---------------- tensor-core flash attention: 128 queries, 8 warps -------------
#define AP 68
// ma(1024) + km(128) + Qs(128*AP) + Ps(128*AP) + Kb(2*64*AP) + Vb(2*64*AP)
#define ATTN_SMEM ((1024 + 128 + 2*128*AP + 4*64*AP) * 4)

__global__ __launch_bounds__(256) void attn_kernel(
    const float* __restrict__ Q, const float* __restrict__ Kg, const float* __restrict__ Vg,
    const float* __restrict__ age, const float* __restrict__ mod_age,
    float* __restrict__ Y)
{
    extern __shared__ float smn[];
    float* ma = smn;                      // 1024
    int*   km = (int*)(smn + 1024);       // 128
    float* Qs = smn + 1024 + 128;         // 128*AP
    float* Ps = Qs + 128*AP;              // 128*AP
    float* Kb = Ps + 128*AP;              // 2*64*AP
    float* Vb = Kb + 2*64*AP;             // 2*64*AP

    int blk = blockIdx.x;
    int qt   = blk & 7;                   // 8 query tiles of 128
    int hd_i = (blk >> 3) % NH;
    int b    = blk / (8*NH);
    int tid  = threadIdx.x;
    int lane = tid & 31, warp = tid >> 5; // 8 warps
    int g = lane >> 2, c = lane & 3;
    int wr = warp * 16;                   // warp rows 0..112

    for (int i = tid; i < LS; i += 256) ma[i] = mod_age[b*LS + i];
    __syncthreads();

    if (tid < 128) {
        float a = age[b*LM + qt*128 + tid];
        int lo = 0, hi = LS;
        while (lo < hi) { int mid = (lo+hi) >> 1; if (ma[mid] <= a) lo = mid+1; else hi = mid; }
        km[tid] = lo;
    }
    __syncthreads();
    // ages sorted per batch -> last query of the tile has the max prefix
    int kmax_blk = km[127];
    #pragma unroll 16
    for (int i = 0; i < 128; i++) kmax_blk = max(kmax_blk, km[i]);

    int tq = b*LM + qt*128;
    // Q tile: 128 rows x 64 floats = 2048 16B chunks, 8 per thread
    #pragma unroll
    for (int i = 0; i < 8; i++) {
        int f = tid + i*256;              // 0..2047
        int r = f >> 4, q4 = (f & 15) << 2;
        cp16(Qs + r*AP + q4, Q + (size_t)(tq+r)*NE + hd_i*HD + q4);
    }

    const size_t kvbase = (size_t)(b*LS)*NE + hd_i*HD;
    int ntile = (kmax_blk + 63) >> 6;

    // prefetch K/V tile 0: 64 rows = 1024 chunks, 4 per thread
    if (ntile > 0) {
        #pragma unroll
        for (int i = 0; i < 4; i++) {
            int f = tid + i*256;
            int r = f >> 4, q4 = (f & 15) << 2;
            cp16(Kb + r*AP + q4, Kg + kvbase + (size_t)r*NE + q4);
            cp16(Vb + r*AP + q4, Vg + kvbase + (size_t)r*NE + q4);
        }
    }
    asm volatile("cp.async.commit_group;");

    float m0 = -1e30f, m1 = -1e30f, l0 = 0.f, l1 = 0.f;
    float Oacc[8][4];
    #pragma unroll
    for (int ni = 0; ni < 8; ni++)
        #pragma unroll
        for (int r = 0; r < 4; r++) Oacc[ni][r] = 0.f;

    int km0 = km[wr + g];
    int km1 = km[wr + g + 8];

    for (int t = 0; t < ntile; t++) {
        int bf = t & 1;
        if (t + 1 < ntile) {
            int j1 = (t+1) * 64;
            int nb = bf ^ 1;
            #pragma unroll
            for (int i = 0; i < 4; i++) {
                int f = tid + i*256;
                int r = f >> 4, q4 = (f & 15) << 2;
                cp16(Kb + nb*64*AP + r*AP + q4, Kg + kvbase + (size_t)(j1+r)*NE + q4);
                cp16(Vb + nb*64*AP + r*AP + q4, Vg + kvbase + (size_t)(j1+r)*NE + q4);
            }
            asm volatile("cp.async.commit_group;");
            asm volatile("cp.async.wait_group 1;");
        } else {
            asm volatile("cp.async.wait_group 0;");
        }
        __syncthreads();

        const float* Ks = Kb + bf*64*AP;
        const float* Vs = Vb + bf*64*AP;
        int j0 = t * 64;

        float Sacc[8][4];
        #pragma unroll
        for (int ni = 0; ni < 8; ni++)
            #pragma unroll
            for (int r = 0; r < 4; r++) Sacc[ni][r] = 0.f;

        #pragma unroll
        for (int kk = 0; kk < 64; kk += 8) {
            uint32_t a0 = __float_as_uint(Qs[(wr+g  )*AP + kk + c  ]);
            uint32_t a1 = __float_as_uint(Qs[(wr+g+8)*AP + kk + c  ]);
            uint32_t a2 = __float_as_uint(Qs[(wr+g  )*AP + kk + c+4]);
            uint32_t a3 = __float_as_uint(Qs[(wr+g+8)*AP + kk + c+4]);
            #pragma unroll
            for (int ni = 0; ni < 8; ni++) {
                uint32_t b0 = __float_as_uint(Ks[(ni*8+g)*AP + kk + c  ]);
                uint32_t b1 = __float_as_uint(Ks[(ni*8+g)*AP + kk + c+4]);
                asm volatile(
                    "mma.sync.aligned.m16n8k8.row.col.f32.tf32.tf32.f32 "
                    "{%0,%1,%2,%3}, {%4,%5,%6,%7}, {%8,%9}, {%0,%1,%2,%3};"
                    : "+f"(Sacc[ni][0]), "+f"(Sacc[ni][1]), "+f"(Sacc[ni][2]), "+f"(Sacc[ni][3])
                    : "r"(a0), "r"(a1), "r"(a2), "r"(a3), "r"(b0), "r"(b1));
            }
        }

        #pragma unroll
        for (int hh = 0; hh < 2; hh++) {
            int row = wr + g + hh*8;
            int kmr = hh ? km1 : km0;
            float mold = hh ? m1 : m0;

            float mx = -1e30f;
            #pragma unroll
            for (int ni = 0; ni < 8; ni++) {
                int c0 = j0 + ni*8 + 2*c;
                float s0 = (c0   < kmr) ? Sacc[ni][hh*2  ] * 0.125f : -1e30f;
                float s1 = (c0+1 < kmr) ? Sacc[ni][hh*2+1] * 0.125f : -1e30f;
                Sacc[ni][hh*2] = s0; Sacc[ni][hh*2+1] = s1;
                mx = fmaxf(mx, fmaxf(s0, s1));
            }
            mx = fmaxf(mx, __shfl_xor_sync(0xffffffffu, mx, 1));
            mx = fmaxf(mx, __shfl_xor_sync(0xffffffffu, mx, 2));
            float mnew = fmaxf(mold, mx);
            float alpha = __expf(mold - mnew);

            float lsum = 0.f;
            #pragma unroll
            for (int ni = 0; ni < 8; ni++) {
                int c0 = j0 + ni*8 + 2*c;
                float p0 = (c0   < kmr) ? __expf(Sacc[ni][hh*2  ] - mnew) : 0.f;
                float p1 = (c0+1 < kmr) ? __expf(Sacc[ni][hh*2+1] - mnew) : 0.f;
                lsum += p0 + p1;
                *(float2*)(Ps + row*AP + ni*8 + 2*c) = make_float2(roundtf(p0), roundtf(p1));
            }
            lsum += __shfl_xor_sync(0xffffffffu, lsum, 1);
            lsum += __shfl_xor_sync(0xffffffffu, lsum, 2);

            if (hh) { l1 = l1*alpha + lsum; m1 = mnew; }
            else    { l0 = l0*alpha + lsum; m0 = mnew; }
            #pragma unroll
            for (int ni = 0; ni < 8; ni++) {
                Oacc[ni][hh*2  ] *= alpha;
                Oacc[ni][hh*2+1] *= alpha;
            }
        }
        __syncwarp();

        #pragma unroll
        for (int kk = 0; kk < 64; kk += 8) {
            uint32_t a0 = __float_as_uint(Ps[(wr+g  )*AP + kk + c  ]);
            uint32_t a1 = __float_as_uint(Ps[(wr+g+8)*AP + kk + c  ]);
            uint32_t a2 = __float_as_uint(Ps[(wr+g  )*AP + kk + c+4]);
            uint32_t a3 = __float_as_uint(Ps[(wr+g+8)*AP + kk + c+4]);
            #pragma unroll
            for (int ni = 0; ni < 8; ni++) {
                uint32_t b0 = __float_as_uint(Vs[(kk+c  )*AP + ni*8 + g]);
                uint32_t b1 = __float_as_uint(Vs[(kk+c+4)*AP + ni*8 + g]);
                asm volatile(
                    "mma.sync.aligned.m16n8k8.row.col.f32.tf32.tf32.f32 "
                    "{%0,%1,%2,%3}, {%4,%5,%6,%7}, {%8,%9}, {%0,%1,%2,%3};"
                    : "+f"(Oacc[ni][0]), "+f"(Oacc[ni][1]), "+f"(Oacc[ni][2]), "+f"(Oacc[ni][3])
                    : "r"(a0), "r"(a1), "r"(a2), "r"(a3), "r"(b0), "r"(b1));
            }
        }
        __syncthreads();
    }

    float inv0 = (l0 > 0.f) ? 1.0f / l0 : 0.f;
    float inv1 = (l1 > 0.f) ? 1.0f / l1 : 0.f;
    #pragma unroll
    for (int hh = 0; hh < 2; hh++) {
        int row = wr + g + hh*8;
        float inv = hh ? inv1 : inv0;
        float* yp = Y + (size_t)(tq + row)*NE + hd_i*HD;
        #pragma unroll
        for (int ni = 0; ni < 8; ni++) {
            float v0 = roundtf(Oacc[ni][hh*2  ] * inv);
            float v1 = roundtf(Oacc[ni][hh*2+1] * inv);
            *(float2*)(yp + ni*8 + 2*c) = make_float2(v0, v1);
        }
    }
}

// ---------------- launch -------------------------------------------------------
extern "C" void kernel_launch(void* const* d_in, const int* in_sizes, int n_in,
                              void* d_out, int out_size) {
    const float* x       = (const float*)d_in[0];
    const float* age     = (const float*)d_in[1];
    const int*   mod_idx = (const int*)  d_in[2];
    const float* mod_age = (const float*)d_in[3];
    const float* m2      = (const float*)d_in[4];
    const float* m3      = (const float*)d_in[5];
    const float* ln0_w = (const float*)d_in[6],  *ln0_b = (const float*)d_in[7];
    const float* ln1_w = (const float*)d_in[8],  *ln1_b = (const float*)d_in[9];
    const float* ln2_w = (const float*)d_in[10], *ln2_b = (const float*)d_in[11];
    const float* q_w  = (const float*)d_in[12], *q_b  = (const float*)d_in[13];
    const float* k_w  = (const float*)d_in[14], *k_b  = (const float*)d_in[15];
    const float* v_w  = (const float*)d_in[16], *v_b  = (const float*)d_in[17];
    const float* c_w  = (const float*)d_in[18], *c_b  = (const float*)d_in[19];
    const float* fc_w = (const float*)d_in[20], *fc_b = (const float*)d_in[21];
    const float* pj_w = (const float*)d_in[22], *pj_b = (const float*)d_in[23];
    float* out = (float*)d_out;

    float *p_sn,*p_xn,*p_q,*p_k,*p_v,*p_y,*p_x2,*p_h1,*p_h2;
    int *p_code;
    cudaGetSymbolAddress((void**)&p_sn,  g_sn);
    cudaGetSymbolAddress((void**)&p_xn,  g_xn);
    cudaGetSymbolAddress((void**)&p_q,   g_q);
    cudaGetSymbolAddress((void**)&p_k,   g_k);
    cudaGetSymbolAddress((void**)&p_v,   g_v);
    cudaGetSymbolAddress((void**)&p_y,   g_y);
    cudaGetSymbolAddress((void**)&p_x2,  g_x2);
    cudaGetSymbolAddress((void**)&p_h1,  g_h1);
    cudaGetSymbolAddress((void**)&p_h2,  g_h2);
    cudaGetSymbolAddress((void**)&p_code, g_code);

    static bool attr_set = false;
    if (!attr_set) {
        cudaFuncSetAttribute(attn_kernel, cudaFuncAttributeMaxDynamicSharedMemorySize, ATTN_SMEM);
        attr_set = true;
    }

    scan_kernel<<<BB, LS>>>(mod_idx, p_code);
    ln_pair_kernel<<<2*NT, 256>>>(p_code, m2, m3, ln0_w, ln0_b, x, ln1_w, ln1_b, p_sn, p_xn);

    dim3 gqkv(NE/128, NT/128, 3);
    mma_gemm_qkv<<<gqkv, 256>>>(p_xn, p_sn, q_w, k_w, v_w, q_b, k_b, v_b, p_q, p_k, p_v);

    attn_kernel<<<BB*NH*8, 256, ATTN_SMEM>>>(p_q, p_k, p_v, age, mod_age, p_y);

    dim3 g768(NE/128, NT/128);
    mma_gemm<<<g768, 256>>>(p_y, c_w, c_b, x, p_x2, NE, NE, 0);
    ln_kernel<<<NT, 256>>>(p_x2, ln2_w, ln2_b, p_h1);

    dim3 g3072(4*NE/128, NT/128);
    mma_gemm<<<g3072, 256>>>(p_h1, fc_w, fc_b, nullptr, p_h2, 4*NE, NE, 1);

    dim3 gproj(NE/128, NT/128, 2);
    mma_gemm_splitk<<<gproj, 256>>>(p_h2, pj_w, p_q, p_k, NE, 2*NE, 4*NE);
    int n4 = NT*NE/4;
    addsplit_kernel<<<(n4 + 255)/256, 256>>>((const float4*)p_q, (const float4*)p_k,
                                             (const float4*)p_x2, pj_b,
                                             (float4*)out, n4, NE/4);
}